// round 4
// baseline (speedup 1.0000x reference)
#include <cuda_runtime.h>
#include <math.h>

// ---------------------------------------------------------------------------
// Encoder_conv2: 5-level grid encoder, fused single kernel.
//   per level: a = tanh(depthwise_conv3x3(F)); out_l = sum_cell bilinear(a[cell], p+0.5*cell)
// Merged-lattice trick: the 2-cell sum is piecewise bilinear on the half-int
// lattice -> per level build G[(2r)^2][4ch] (f32, in smem, once per block).
// Main loop: one thread per OUTPUT float4 (f = p*5 + l) so stores are fully
// coalesced; per-level constants via a 5-entry smem table (one LDS.128).
// ---------------------------------------------------------------------------

#define NTHR 1024

// a texels cumulative: 2*r*r per level (r = 8,12,20,18,32)
#define ATEXT 3912
// G texel bases: (2r)^2 per level
#define GTEX0 0
#define GTEX1 256
#define GTEX2 832
#define GTEX3 2432
#define GTEX4 3728
#define GTEXT 7824

#define SG_BYTES   (GTEXT * 16)              // 125184
#define SA_BYTES   (ATEXT * 16)              // 62592
#define TBL_OFF    (SG_BYTES + SA_BYTES)
#define SMEM_BYTES (TBL_OFF + 5 * 16)        // 187856

__global__ void __launch_bounds__(NTHR, 1)
k_fused(const float* __restrict__ F0, const float* __restrict__ F1,
        const float* __restrict__ F2, const float* __restrict__ F3,
        const float* __restrict__ F4, const float* __restrict__ W,
        const float* __restrict__ X, const float* __restrict__ Y,
        float* __restrict__ out, int npts) {
    extern __shared__ unsigned char smraw[];
    float4* sg   = reinterpret_cast<float4*>(smraw);             // merged grids
    float4* sa   = reinterpret_cast<float4*>(smraw + SG_BYTES);  // conv scratch
    uint4*  stbl = reinterpret_cast<uint4*> (smraw + TBL_OFF);   // per-level consts

    const int tid = threadIdx.x;

    const float* Fs[5] = {F0, F1, F2, F3, F4};
    const int resa [5] = {8, 12, 20, 18, 32};
    const int acum [6] = {0, 128, 416, 1216, 1864, 3912};
    const int gbase[5] = {GTEX0, GTEX1, GTEX2, GTEX3, GTEX4};

    // conv weights (broadcast; fully unrolled use below)
    float w[36];
    #pragma unroll
    for (int i = 0; i < 36; i++) w[i] = W[i];

    // per-level constant table: {scale bits, n2, level base byte offset}
    if (tid < 5) {
        int r = resa[tid];
        stbl[tid] = make_uint4(__float_as_uint((float)(2 * r - 2)),
                               (unsigned)(2 * r), (unsigned)(gbase[tid] * 16), 0u);
    }

    // ---- Phase 1a: depthwise conv3x3 (SAME, zero-pad) + tanh -> sa ----
    for (int tex = tid; tex < ATEXT; tex += NTHR) {
        int l = 0;
        #pragma unroll
        for (int q = 0; q < 4; q++) if (tex >= acum[q + 1]) l = q + 1;
        const float* Fl = Fs[l];
        const int r = resa[l];
        int rem = tex - acum[l];
        int rr  = r * r;
        int j   = rem / rr;
        int yx  = rem - j * rr;
        int y   = yx / r;
        int x   = yx - y * r;

        float oc[4];
        #pragma unroll
        for (int c = 0; c < 4; c++) {
            float s = 0.f;
            #pragma unroll
            for (int dy = 0; dy < 3; dy++) {
                int yy = y + dy - 1;
                if (yy < 0 || yy >= r) continue;
                #pragma unroll
                for (int dx = 0; dx < 3; dx++) {
                    int xx = x + dx - 1;
                    if (xx < 0 || xx >= r) continue;
                    s += __ldg(&Fl[((j * 4 + c) * r + yy) * r + xx]) * w[c * 9 + dy * 3 + dx];
                }
            }
            oc[c] = tanhf(s);
        }
        sa[tex] = make_float4(oc[0], oc[1], oc[2], oc[3]);
    }
    __syncthreads();

    // ---- Phase 1b: merged half-lattice node grid -> sg ----
    // G[k][m] = sum_j bilinear_clamped(a[j], (m+j)/2, (k+j)/2)
    for (int tex = tid; tex < GTEXT; tex += NTHR) {
        int l = 0;
        {
            const int gcum[6] = {GTEX0, GTEX1, GTEX2, GTEX3, GTEX4, GTEXT};
            #pragma unroll
            for (int q = 0; q < 4; q++) if (tex >= gcum[q + 1]) l = q + 1;
        }
        const int r  = resa[l];
        const int rr = r * r;
        const int n2 = 2 * r;
        int rem = tex - gbase[l];
        int k   = rem / n2;
        int m   = rem - k * n2;

        float ax = 0.f, ay = 0.f, az = 0.f, aw = 0.f;
        #pragma unroll
        for (int j = 0; j < 2; j++) {
            float px = 0.5f * (float)(m + j);
            float py = 0.5f * (float)(k + j);
            float fx = floorf(px), fy = floorf(py);
            float wx = px - fx,    wy = py - fy;
            int ix0 = (int)fx, iy0 = (int)fy;
            int x0 = min(max(ix0,     0), r - 1);
            int x1 = min(max(ix0 + 1, 0), r - 1);
            int y0 = min(max(iy0,     0), r - 1);
            int y1 = min(max(iy0 + 1, 0), r - 1);
            int base = acum[l] + j * rr;
            float4 c00 = sa[base + y0 * r + x0];
            float4 c01 = sa[base + y0 * r + x1];
            float4 c10 = sa[base + y1 * r + x0];
            float4 c11 = sa[base + y1 * r + x1];
            float w00 = (1.f - wx) * (1.f - wy);
            float w01 = wx * (1.f - wy);
            float w10 = (1.f - wx) * wy;
            float w11 = wx * wy;
            ax += c00.x * w00 + c01.x * w01 + c10.x * w10 + c11.x * w11;
            ay += c00.y * w00 + c01.y * w01 + c10.y * w10 + c11.y * w11;
            az += c00.z * w00 + c01.z * w01 + c10.z * w10 + c11.z * w11;
            aw += c00.w * w00 + c01.w * w01 + c10.w * w10 + c11.w * w11;
        }
        sg[tex] = make_float4(ax, ay, az, aw);
    }
    __syncthreads();

    // ---- Phase 2: one thread per output float4 (f = p*5 + l). ----
    const int ntot = npts * 5;
    const int stride = gridDim.x * NTHR;
    float4* og = reinterpret_cast<float4*>(out);

    for (int f = blockIdx.x * NTHR + tid; f < ntot; f += stride) {
        unsigned uf = (unsigned)f;
        unsigned p  = uf / 5u;
        int l = (int)(uf - p * 5u);

        uint4 tb = stbl[l];
        float sx = __uint_as_float(tb.x);
        int   n2 = (int)tb.y;
        int   gb = (int)tb.z;

        float hx = __ldg(&X[p]);   // x in [0,1): ix_ref = x*(r-1); doubled: h = x*(2r-2)
        float hy = __ldg(&Y[p]);
        float h = hx * sx;
        float v = hy * sx;
        float fm = floorf(h), fk = floorf(v);
        int m0 = (int)fm, k0 = (int)fk;      // no clamps needed: h in [0, 2r-2)
        float wx = h - fm, wy = v - fk;

        const float4* g = reinterpret_cast<const float4*>(smraw + gb) + (k0 * n2 + m0);
        float4 c00 = g[0];
        float4 c01 = g[1];
        float4 c10 = g[n2];
        float4 c11 = g[n2 + 1];

        float wxb = 1.f - wx, wyb = 1.f - wy;
        float w00 = wxb * wyb;
        float w01 = wx  * wyb;
        float w10 = wxb * wy;
        float w11 = wx  * wy;

        float4 o;
        o.x = c00.x * w00 + c01.x * w01 + c10.x * w10 + c11.x * w11;
        o.y = c00.y * w00 + c01.y * w01 + c10.y * w10 + c11.y * w11;
        o.z = c00.z * w00 + c01.z * w01 + c10.z * w10 + c11.z * w11;
        o.w = c00.w * w00 + c01.w * w01 + c10.w * w10 + c11.w * w11;

        og[f] = o;   // fully coalesced: consecutive lanes -> consecutive float4
    }
}

// ---------------------------------------------------------------------------
extern "C" void kernel_launch(void* const* d_in, const int* in_sizes, int n_in,
                              void* d_out, int out_size) {
    const float* X = nullptr;
    const float* Yv = nullptr;
    const float* W = nullptr;
    const float* F[5] = {nullptr, nullptr, nullptr, nullptr, nullptr};
    int npts = 0;

    for (int i = 0; i < n_in; i++) {
        int s = in_sizes[i];
        const float* p = (const float*)d_in[i];
        if (s == 36)        W    = p;
        else if (s == 512)  F[0] = p;
        else if (s == 1152) F[1] = p;
        else if (s == 3200) F[2] = p;
        else if (s == 2592) F[3] = p;
        else if (s == 8192) F[4] = p;
        else {
            if (!X) { X = p; npts = s; }
            else     Yv = p;
        }
    }

    static int nsm = 0;
    static bool init_done = false;
    if (!init_done) {
        cudaFuncSetAttribute(k_fused, cudaFuncAttributeMaxDynamicSharedMemorySize, SMEM_BYTES);
        cudaDeviceGetAttribute(&nsm, cudaDevAttrMultiProcessorCount, 0);
        if (nsm <= 0) nsm = 148;
        init_done = true;
    }

    k_fused<<<nsm, NTHR, SMEM_BYTES>>>(F[0], F[1], F[2], F[3], F[4], W,
                                       X, Yv, (float*)d_out, npts);
}

// round 6
// speedup vs baseline: 1.0739x; 1.0739x over previous
#include <cuda_runtime.h>
#include <cuda_fp16.h>
#include <math.h>

// ---------------------------------------------------------------------------
// Encoder_conv2: 5-level grid encoder, fused single kernel.
//   per level: a = tanh(depthwise_conv3x3(F)); out_l = sum_cell bilinear(a[cell], p+0.5*cell)
// Merged half-integer-lattice trick: build G[(2r)^2][4ch] per level in smem.
// Grids stored as scaled fp16 in TWO parity copies of 16-byte corner-PAIR
// chunks: copy A = texels (2j,2j+1), copy B = (2j+1,2j+2). Any bilinear fetch
// is then exactly 2 aligned LDS.128 (top pair + bottom pair).
// Main loop: one thread per OUTPUT float4 (f = p*5 + l) -> coalesced stores.
// ---------------------------------------------------------------------------

#define NTHR 1024

// a texels cumulative: 2*r*r per level (r = 8,12,20,18,32)
#define ATEXT 3912
// per-level grid byte bases: level l occupies (2r)^2 * 16 bytes (2 copies x 8B texel)
#define GB0 0
#define GB1 4096
#define GB2 13312
#define GB3 38912
#define GB4 59648
#define GBT 125184

#define SA_OFF    GBT
#define SA_BYTES  (ATEXT * 16)             // 62592 f32 conv scratch
#define TBL_OFF   (SA_OFF + SA_BYTES)
#define SMEM_BYTES (TBL_OFF + 5 * 16)      // 187936

#define SCALE_UP 1024.0f
#define SCALE_DN (1.0f / 1024.0f)

__global__ void __launch_bounds__(NTHR, 1)
k_fused(const float* __restrict__ F0, const float* __restrict__ F1,
        const float* __restrict__ F2, const float* __restrict__ F3,
        const float* __restrict__ F4, const float* __restrict__ W,
        const float* __restrict__ X, const float* __restrict__ Y,
        float* __restrict__ out, int npts) {
    extern __shared__ unsigned char smraw[];
    float4* sa   = reinterpret_cast<float4*>(smraw + SA_OFF);   // conv scratch
    uint4*  stbl = reinterpret_cast<uint4*> (smraw + TBL_OFF);  // per-level consts

    const int tid = threadIdx.x;

    const float* Fs[5] = {F0, F1, F2, F3, F4};
    const int resa [5] = {8, 12, 20, 18, 32};
    const int acum [6] = {0, 128, 416, 1216, 1864, 3912};
    const int gbyte[5] = {GB0, GB1, GB2, GB3, GB4};

    // conv weights (broadcast)
    float w[36];
    #pragma unroll
    for (int i = 0; i < 36; i++) w[i] = W[i];

    // per-level table: {scale bits, row bytes (n2*8), level base byte, copy size}
    if (tid < 5) {
        int r  = resa[tid];
        int n2 = 2 * r;
        stbl[tid] = make_uint4(__float_as_uint((float)(n2 - 2)),
                               (unsigned)(n2 * 8),
                               (unsigned)gbyte[tid],
                               (unsigned)(n2 * n2 * 8));
    }

    // ---- Phase 1a: depthwise conv3x3 (SAME, zero-pad) + tanh -> sa (f32) ----
    for (int tex = tid; tex < ATEXT; tex += NTHR) {
        int l = 0;
        #pragma unroll
        for (int q = 0; q < 4; q++) if (tex >= acum[q + 1]) l = q + 1;
        const float* Fl = Fs[l];
        const int r = resa[l];
        int rem = tex - acum[l];
        int rr  = r * r;
        int j   = rem / rr;
        int yx  = rem - j * rr;
        int y   = yx / r;
        int x   = yx - y * r;

        float oc[4];
        #pragma unroll
        for (int c = 0; c < 4; c++) {
            float s = 0.f;
            #pragma unroll
            for (int dy = 0; dy < 3; dy++) {
                int yy = y + dy - 1;
                if (yy < 0 || yy >= r) continue;
                #pragma unroll
                for (int dx = 0; dx < 3; dx++) {
                    int xx = x + dx - 1;
                    if (xx < 0 || xx >= r) continue;
                    s += __ldg(&Fl[((j * 4 + c) * r + yy) * r + xx]) * w[c * 9 + dy * 3 + dx];
                }
            }
            oc[c] = tanhf(s);
        }
        sa[tex] = make_float4(oc[0], oc[1], oc[2], oc[3]);
    }
    __syncthreads();

    // ---- Phase 1b: merged half-lattice node grid -> packed fp16 copies ----
    // node (k,m): G = sum_j bilinear_clamped(a[j], (m+j)/2, (k+j)/2), scaled 2^10.
    {
        // total nodes across levels: sum (2r)^2 = 7824
        const int ncum[6] = {0, 256, 832, 2432, 3728, 7824};
        for (int tex = tid; tex < 7824; tex += NTHR) {
            int l = 0;
            #pragma unroll
            for (int q = 0; q < 4; q++) if (tex >= ncum[q + 1]) l = q + 1;
            const int r  = resa[l];
            const int rr = r * r;
            const int n2 = 2 * r;
            int rem = tex - ncum[l];
            int k   = rem / n2;
            int m   = rem - k * n2;

            float ax = 0.f, ay = 0.f, az = 0.f, aw = 0.f;
            #pragma unroll
            for (int j = 0; j < 2; j++) {
                float px = 0.5f * (float)(m + j);
                float py = 0.5f * (float)(k + j);
                float fx = floorf(px), fy = floorf(py);
                float wx = px - fx,    wy = py - fy;
                int ix0 = (int)fx, iy0 = (int)fy;
                int x0 = min(max(ix0,     0), r - 1);
                int x1 = min(max(ix0 + 1, 0), r - 1);
                int y0 = min(max(iy0,     0), r - 1);
                int y1 = min(max(iy0 + 1, 0), r - 1);
                int base = acum[l] + j * rr;
                float4 c00 = sa[base + y0 * r + x0];
                float4 c01 = sa[base + y0 * r + x1];
                float4 c10 = sa[base + y1 * r + x0];
                float4 c11 = sa[base + y1 * r + x1];
                float w00 = (1.f - wx) * (1.f - wy);
                float w01 = wx * (1.f - wy);
                float w10 = (1.f - wx) * wy;
                float w11 = wx * wy;
                ax += c00.x * w00 + c01.x * w01 + c10.x * w10 + c11.x * w11;
                ay += c00.y * w00 + c01.y * w01 + c10.y * w10 + c11.y * w11;
                az += c00.z * w00 + c01.z * w01 + c10.z * w10 + c11.z * w11;
                aw += c00.w * w00 + c01.w * w01 + c10.w * w10 + c11.w * w11;
            }
            __half2 h01 = __floats2half2_rn(ax * SCALE_UP, ay * SCALE_UP);
            __half2 h23 = __floats2half2_rn(az * SCALE_UP, aw * SCALE_UP);
            uint2 val;
            val.x = *reinterpret_cast<unsigned int*>(&h01);
            val.y = *reinterpret_cast<unsigned int*>(&h23);

            const int rowb  = n2 * 8;
            const int asize = n2 * n2 * 8;
            unsigned char* lb = smraw + gbyte[l];
            // copy A: texel m at k*rowb + m*8
            *reinterpret_cast<uint2*>(lb + k * rowb + m * 8) = val;
            // copy B (shifted pairs): texel m (m>=1) at Asize + k*rowb + (m-1)*8
            if (m >= 1)
                *reinterpret_cast<uint2*>(lb + asize + k * rowb + (m - 1) * 8) = val;
        }
    }
    __syncthreads();

    // ---- Phase 2: one thread per output float4 (f = p*5 + l). ----
    const int ntot = npts * 5;
    const int stride = gridDim.x * NTHR;
    float4* og = reinterpret_cast<float4*>(out);

    for (int f = blockIdx.x * NTHR + tid; f < ntot; f += stride) {
        unsigned uf = (unsigned)f;
        unsigned p  = uf / 5u;
        int l = (int)(uf - p * 5u);

        uint4 tb = stbl[l];
        float    sx    = __uint_as_float(tb.x);
        unsigned rowb  = tb.y;
        unsigned lbase = tb.z;
        unsigned asize = tb.w;

        float hx = __ldg(&X[p]);   // x in [0,1): doubled lattice coord h = x*(2r-2)
        float hy = __ldg(&Y[p]);
        float h = hx * sx;
        float v = hy * sx;
        float fm = floorf(h), fk = floorf(v);
        int m0 = (int)fm, k0 = (int)fk;          // in range, no clamps needed
        float wx = h - fm, wy = v - fk;

        unsigned addr = lbase + (unsigned)(m0 & 1) * asize
                      + (unsigned)k0 * rowb + (unsigned)(m0 & ~1) * 8u;
        uint4 t0 = *reinterpret_cast<const uint4*>(smraw + addr);         // c00,c01
        uint4 t1 = *reinterpret_cast<const uint4*>(smraw + addr + rowb);  // c10,c11

        float2 a00 = __half22float2(*reinterpret_cast<__half2*>(&t0.x));
        float2 b00 = __half22float2(*reinterpret_cast<__half2*>(&t0.y));
        float2 a01 = __half22float2(*reinterpret_cast<__half2*>(&t0.z));
        float2 b01 = __half22float2(*reinterpret_cast<__half2*>(&t0.w));
        float2 a10 = __half22float2(*reinterpret_cast<__half2*>(&t1.x));
        float2 b10 = __half22float2(*reinterpret_cast<__half2*>(&t1.y));
        float2 a11 = __half22float2(*reinterpret_cast<__half2*>(&t1.z));
        float2 b11 = __half22float2(*reinterpret_cast<__half2*>(&t1.w));

        // fold 2^-10 into y-weights (exact power of two)
        float wyS = wy * SCALE_DN;
        float wyB = SCALE_DN - wyS;       // (1-wy)*2^-10
        float wxb = 1.f - wx;
        float w00 = wxb * wyB;
        float w01 = wx  * wyB;
        float w10 = wxb * wyS;
        float w11 = wx  * wyS;

        float4 o;
        o.x = a00.x * w00 + a01.x * w01 + a10.x * w10 + a11.x * w11;
        o.y = a00.y * w00 + a01.y * w01 + a10.y * w10 + a11.y * w11;
        o.z = b00.x * w00 + b01.x * w01 + b10.x * w10 + b11.x * w11;
        o.w = b00.y * w00 + b01.y * w01 + b10.y * w10 + b11.y * w11;

        og[f] = o;   // fully coalesced
    }
}

// ---------------------------------------------------------------------------
extern "C" void kernel_launch(void* const* d_in, const int* in_sizes, int n_in,
                              void* d_out, int out_size) {
    const float* X = nullptr;
    const float* Yv = nullptr;
    const float* W = nullptr;
    const float* F[5] = {nullptr, nullptr, nullptr, nullptr, nullptr};
    int npts = 0;

    for (int i = 0; i < n_in; i++) {
        int s = in_sizes[i];
        const float* p = (const float*)d_in[i];
        if (s == 36)        W    = p;
        else if (s == 512)  F[0] = p;
        else if (s == 1152) F[1] = p;
        else if (s == 3200) F[2] = p;
        else if (s == 2592) F[3] = p;
        else if (s == 8192) F[4] = p;
        else {
            if (!X) { X = p; npts = s; }
            else     Yv = p;
        }
    }

    static int nsm = 0;
    static bool init_done = false;
    if (!init_done) {
        cudaFuncSetAttribute(k_fused, cudaFuncAttributeMaxDynamicSharedMemorySize, SMEM_BYTES);
        cudaDeviceGetAttribute(&nsm, cudaDevAttrMultiProcessorCount, 0);
        if (nsm <= 0) nsm = 148;
        init_done = true;
    }

    k_fused<<<nsm, NTHR, SMEM_BYTES>>>(F[0], F[1], F[2], F[3], F[4], W,
                                       X, Yv, (float*)d_out, npts);
}